// round 2
// baseline (speedup 1.0000x reference)
#include <cuda_runtime.h>
#include <math.h>

// Problem constants
#define B  2
#define S  2048
#define D  1024
#define H  16
#define DK 64
#define M_ROWS (B * S)   // 4096

// ---------------- scratch (device globals: allocation-free) ----------------
__device__ float g_Q[M_ROWS * D];
__device__ float g_K[M_ROWS * D];
__device__ float g_V[M_ROWS * D];
__device__ float g_C[M_ROWS * D];

// ---------------- GEMM: C[M,N] = A[M,K] @ W[K,N] + bias[N] ----------------
#define BM 128
#define BN 128
#define BK 16
#define TM 8
#define TN 8

__global__ __launch_bounds__(256) void gemm_bias_kernel(
    const float* __restrict__ A, const float* __restrict__ W,
    const float* __restrict__ bias, float* __restrict__ C,
    int M, int N, int K)
{
    __shared__ float As[BK][BM + 4];
    __shared__ float Bs[BK][BN];

    const int tid = threadIdx.x;
    const int block_m = blockIdx.y * BM;
    const int block_n = blockIdx.x * BN;
    const int tx = tid & 15;          // 0..15 -> column group
    const int ty = tid >> 4;          // 0..15 -> row group

    float acc[TM][TN];
#pragma unroll
    for (int i = 0; i < TM; i++)
#pragma unroll
        for (int j = 0; j < TN; j++) acc[i][j] = 0.f;

    for (int k0 = 0; k0 < K; k0 += BK) {
        // Load A tile (BM x BK) transposed into As[k][m]
#pragma unroll
        for (int i = 0; i < 2; i++) {
            int idx = tid + i * 256;          // 0..511
            int m   = idx >> 2;               // 0..127
            int kv  = (idx & 3) * 4;          // 0,4,8,12
            float4 a = *(const float4*)&A[(size_t)(block_m + m) * K + k0 + kv];
            As[kv + 0][m] = a.x;
            As[kv + 1][m] = a.y;
            As[kv + 2][m] = a.z;
            As[kv + 3][m] = a.w;
        }
        // Load B tile (BK x BN) into Bs[k][n] (coalesced)
#pragma unroll
        for (int i = 0; i < 2; i++) {
            int idx = tid + i * 256;          // 0..511
            int kk  = idx >> 5;               // 0..15
            int nv  = (idx & 31) * 4;         // 0..124
            *(float4*)&Bs[kk][nv] =
                *(const float4*)&W[(size_t)(k0 + kk) * N + block_n + nv];
        }
        __syncthreads();

#pragma unroll
        for (int k = 0; k < BK; k++) {
            float a_frag[TM], b_frag[TN];
#pragma unroll
            for (int i = 0; i < TM; i += 4)
                *(float4*)&a_frag[i] = *(const float4*)&As[k][ty * TM + i];
#pragma unroll
            for (int j = 0; j < TN; j += 4)
                *(float4*)&b_frag[j] = *(const float4*)&Bs[k][tx * TN + j];
#pragma unroll
            for (int i = 0; i < TM; i++)
#pragma unroll
                for (int j = 0; j < TN; j++)
                    acc[i][j] += a_frag[i] * b_frag[j];
        }
        __syncthreads();
    }

    // Epilogue: add bias, store
#pragma unroll
    for (int i = 0; i < TM; i++) {
        int row = block_m + ty * TM + i;
#pragma unroll
        for (int j = 0; j < TN; j += 4) {
            int col = block_n + tx * TN + j;
            float4 o;
            o.x = acc[i][j + 0] + bias[col + 0];
            o.y = acc[i][j + 1] + bias[col + 1];
            o.z = acc[i][j + 2] + bias[col + 2];
            o.w = acc[i][j + 3] + bias[col + 3];
            *(float4*)&C[(size_t)row * N + col] = o;
        }
    }
}

// ---------------- Attention (flash-style, online softmax) ----------------
// grid: (S/QROWS, H, B), block: QROWS threads (1 thread = 1 query row)
#define QROWS 128
#define KCHUNK 64

__global__ __launch_bounds__(QROWS) void attention_kernel(
    const float* __restrict__ Q, const float* __restrict__ K,
    const float* __restrict__ V, const int* __restrict__ mask,
    float* __restrict__ Ctx)
{
    const int b  = blockIdx.z;
    const int h  = blockIdx.y;
    const int q0 = blockIdx.x * QROWS;
    const int t  = threadIdx.x;

    __shared__ float Ks[KCHUNK][DK];
    __shared__ float Vs[KCHUNK][DK];
    __shared__ int ms[KCHUNK];

    // Load my query row into registers
    const float* Qrow = Q + ((size_t)b * S + q0 + t) * D + h * DK;
    float q[DK];
#pragma unroll
    for (int d = 0; d < DK; d += 4)
        *(float4*)&q[d] = *(const float4*)&Qrow[d];

    float acc[DK];
#pragma unroll
    for (int d = 0; d < DK; d++) acc[d] = 0.f;
    float m = -INFINITY;
    float l = 0.f;
    const float scale = 0.125f;   // 1/sqrt(64)

    for (int kk = 0; kk < S; kk += KCHUNK) {
        // Cooperative load of K/V chunk: 64 x 64 floats each
#pragma unroll
        for (int i = 0; i < 8; i++) {
            int idx = t + i * QROWS;          // 0..1023
            int r   = idx >> 4;               // 0..63
            int cv  = (idx & 15) * 4;         // 0..60
            size_t g = ((size_t)b * S + kk + r) * D + h * DK + cv;
            *(float4*)&Ks[r][cv] = *(const float4*)&K[g];
            *(float4*)&Vs[r][cv] = *(const float4*)&V[g];
        }
        if (t < KCHUNK) ms[t] = mask[(size_t)b * S + kk + t];
        __syncthreads();

        for (int j = 0; j < KCHUNK; j++) {
            float s = 0.f;
#pragma unroll
            for (int d = 0; d < DK; d++) s += q[d] * Ks[j][d];
            bool masked = (ms[j] != 0);
            s = masked ? -INFINITY : s * scale;

            if (s > m) {                       // rare after warmup
                float corr = __expf(m - s);    // exp(-inf)=0 on first hit
                l *= corr;
#pragma unroll
                for (int d = 0; d < DK; d++) acc[d] *= corr;
                m = s;
            }
            float p = masked ? 0.f : __expf(s - m);
            l += p;
#pragma unroll
            for (int d = 0; d < DK; d++) acc[d] += p * Vs[j][d];
        }
        __syncthreads();
    }

    float inv = (l > 0.f) ? (1.f / l) : 0.f;   // fully-masked row -> zeros
    float* out = Ctx + ((size_t)b * S + q0 + t) * D + h * DK;
#pragma unroll
    for (int d = 0; d < DK; d += 4) {
        float4 o;
        o.x = acc[d + 0] * inv;
        o.y = acc[d + 1] * inv;
        o.z = acc[d + 2] * inv;
        o.w = acc[d + 3] * inv;
        *(float4*)&out[d] = o;
    }
}

// ---------------- launch ----------------
extern "C" void kernel_launch(void* const* d_in, const int* in_sizes, int n_in,
                              void* d_out, int out_size)
{
    // metadata order: query, key, value, mask, Wq, bq, Wk, bk, Wv, bv, Wo, bo
    const float* query = (const float*)d_in[0];
    const float* key   = (const float*)d_in[1];
    const float* value = (const float*)d_in[2];
    const int*   mask  = (const int*)d_in[3];
    const float* Wq = (const float*)d_in[4];
    const float* bq = (const float*)d_in[5];
    const float* Wk = (const float*)d_in[6];
    const float* bk = (const float*)d_in[7];
    const float* Wv = (const float*)d_in[8];
    const float* bv = (const float*)d_in[9];
    const float* Wo = (const float*)d_in[10];
    const float* bo = (const float*)d_in[11];
    float* out = (float*)d_out;

    float *qbuf, *kbuf, *vbuf, *cbuf;
    cudaGetSymbolAddress((void**)&qbuf, g_Q);
    cudaGetSymbolAddress((void**)&kbuf, g_K);
    cudaGetSymbolAddress((void**)&vbuf, g_V);
    cudaGetSymbolAddress((void**)&cbuf, g_C);

    dim3 gemm_grid(D / BN, M_ROWS / BM);   // (8, 32)
    gemm_bias_kernel<<<gemm_grid, 256>>>(query, Wq, bq, qbuf, M_ROWS, D, D);
    gemm_bias_kernel<<<gemm_grid, 256>>>(key,   Wk, bk, kbuf, M_ROWS, D, D);
    gemm_bias_kernel<<<gemm_grid, 256>>>(value, Wv, bv, vbuf, M_ROWS, D, D);

    dim3 attn_grid(S / QROWS, H, B);       // (16, 16, 2)
    attention_kernel<<<attn_grid, QROWS>>>(qbuf, kbuf, vbuf, mask, cbuf);

    gemm_bias_kernel<<<gemm_grid, 256>>>(cbuf, Wo, bo, out, M_ROWS, D, D);
}

// round 3
// speedup vs baseline: 1.2943x; 1.2943x over previous
#include <cuda_runtime.h>
#include <math.h>

// Problem constants
#define B  2
#define S  2048
#define D  1024
#define H  16
#define DK 64
#define M_ROWS (B * S)   // 4096

// ---------------- scratch (device globals: allocation-free) ----------------
__device__ float g_Q[M_ROWS * D];
__device__ float g_K[M_ROWS * D];
__device__ float g_V[M_ROWS * D];
__device__ float g_C[M_ROWS * D];

// ---------------- GEMM: C[M,N] = A[M,K] @ W[K,N] + bias[N] ----------------
#define BM 128
#define BN 128
#define BK 16
#define TM 8
#define TN 8

__global__ __launch_bounds__(256) void gemm_bias_kernel(
    const float* __restrict__ A, const float* __restrict__ W,
    const float* __restrict__ bias, float* __restrict__ C,
    int M, int N, int K)
{
    __shared__ float As[BK][BM + 4];
    __shared__ float Bs[BK][BN];

    const int tid = threadIdx.x;
    const int block_m = blockIdx.y * BM;
    const int block_n = blockIdx.x * BN;
    const int tx = tid & 15;
    const int ty = tid >> 4;

    float acc[TM][TN];
#pragma unroll
    for (int i = 0; i < TM; i++)
#pragma unroll
        for (int j = 0; j < TN; j++) acc[i][j] = 0.f;

    for (int k0 = 0; k0 < K; k0 += BK) {
#pragma unroll
        for (int i = 0; i < 2; i++) {
            int idx = tid + i * 256;
            int m   = idx >> 2;
            int kv  = (idx & 3) * 4;
            float4 a = *(const float4*)&A[(size_t)(block_m + m) * K + k0 + kv];
            As[kv + 0][m] = a.x;
            As[kv + 1][m] = a.y;
            As[kv + 2][m] = a.z;
            As[kv + 3][m] = a.w;
        }
#pragma unroll
        for (int i = 0; i < 2; i++) {
            int idx = tid + i * 256;
            int kk  = idx >> 5;
            int nv  = (idx & 31) * 4;
            *(float4*)&Bs[kk][nv] =
                *(const float4*)&W[(size_t)(k0 + kk) * N + block_n + nv];
        }
        __syncthreads();

#pragma unroll
        for (int k = 0; k < BK; k++) {
            float a_frag[TM], b_frag[TN];
#pragma unroll
            for (int i = 0; i < TM; i += 4)
                *(float4*)&a_frag[i] = *(const float4*)&As[k][ty * TM + i];
#pragma unroll
            for (int j = 0; j < TN; j += 4)
                *(float4*)&b_frag[j] = *(const float4*)&Bs[k][tx * TN + j];
#pragma unroll
            for (int i = 0; i < TM; i++)
#pragma unroll
                for (int j = 0; j < TN; j++)
                    acc[i][j] += a_frag[i] * b_frag[j];
        }
        __syncthreads();
    }

#pragma unroll
    for (int i = 0; i < TM; i++) {
        int row = block_m + ty * TM + i;
#pragma unroll
        for (int j = 0; j < TN; j += 4) {
            int col = block_n + tx * TN + j;
            float4 o;
            o.x = acc[i][j + 0] + bias[col + 0];
            o.y = acc[i][j + 1] + bias[col + 1];
            o.z = acc[i][j + 2] + bias[col + 2];
            o.w = acc[i][j + 3] + bias[col + 3];
            *(float4*)&C[(size_t)row * N + col] = o;
        }
    }
}

// ---------------- Attention: tiled flash, 64x64 score tile / block -------
// grid: (S/64, H, B), block: 256 threads, 4x4 microtile per thread.
// SMEM (dynamic): Qt[64][PAD] (Q^T), KPt[64][PAD] (K^T, reused for P^T),
//                 Vs[64][PAD], ms[64].
#define QTILE 64
#define PAD   68

__global__ __launch_bounds__(256) void attention_kernel(
    const float* __restrict__ Q, const float* __restrict__ K,
    const float* __restrict__ V, const int* __restrict__ mask,
    float* __restrict__ Ctx)
{
    extern __shared__ float sm[];
    float* Qt  = sm;                       // [64][PAD], Qt[d][r]
    float* KPt = Qt + QTILE * PAD;         // [64][PAD], Kt[d][c] then Pt[c][r]
    float* Vs  = KPt + QTILE * PAD;        // [64][PAD], Vs[c][d]
    int*   ms  = (int*)(Vs + QTILE * PAD); // [64]

    const int b  = blockIdx.z;
    const int h  = blockIdx.y;
    const int q0 = blockIdx.x * QTILE;
    const int tid = threadIdx.x;
    const int tx = tid & 15;   // 4 cols each
    const int ty = tid >> 4;   // 4 rows each

    const int dg  = tid & 15;  // d-group for tile loads
    const int row = tid >> 4;  // row 0..15, stepped by 16

    // ---- load Q tile transposed: Qt[d][r] ----
#pragma unroll
    for (int i = 0; i < 4; i++) {
        int r = row + i * 16;
        float4 qv = *(const float4*)&Q[((size_t)b * S + q0 + r) * D + h * DK + dg * 4];
        Qt[(dg * 4 + 0) * PAD + r] = qv.x;
        Qt[(dg * 4 + 1) * PAD + r] = qv.y;
        Qt[(dg * 4 + 2) * PAD + r] = qv.z;
        Qt[(dg * 4 + 3) * PAD + r] = qv.w;
    }

    float acc[4][4];
#pragma unroll
    for (int i = 0; i < 4; i++)
#pragma unroll
        for (int j = 0; j < 4; j++) acc[i][j] = 0.f;
    float mrow[4] = {-1e30f, -1e30f, -1e30f, -1e30f};
    float lrow[4] = {0.f, 0.f, 0.f, 0.f};
    const float scale = 0.125f;   // 1/sqrt(64)

    for (int kk = 0; kk < S; kk += QTILE) {
        __syncthreads();  // prior PV reads done before overwriting K/V/P

        // ---- load K tile transposed + V tile natural + mask ----
#pragma unroll
        for (int i = 0; i < 4; i++) {
            int r = row + i * 16;
            size_t g = ((size_t)b * S + kk + r) * D + h * DK + dg * 4;
            float4 kv = *(const float4*)&K[g];
            KPt[(dg * 4 + 0) * PAD + r] = kv.x;
            KPt[(dg * 4 + 1) * PAD + r] = kv.y;
            KPt[(dg * 4 + 2) * PAD + r] = kv.z;
            KPt[(dg * 4 + 3) * PAD + r] = kv.w;
            *(float4*)&Vs[r * PAD + dg * 4] = *(const float4*)&V[g];
        }
        if (tid < QTILE) ms[tid] = mask[(size_t)b * S + kk + tid];
        __syncthreads();

        // ---- QK^T: s[i][j] = sum_d Qt[d][ty4+i] * Kt[d][tx4+j] ----
        float s[4][4];
#pragma unroll
        for (int i = 0; i < 4; i++)
#pragma unroll
            for (int j = 0; j < 4; j++) s[i][j] = 0.f;

#pragma unroll
        for (int d = 0; d < QTILE; d++) {
            float4 a = *(const float4*)&Qt[d * PAD + ty * 4];
            float4 bf = *(const float4*)&KPt[d * PAD + tx * 4];
            float af[4] = {a.x, a.y, a.z, a.w};
            float bfr[4] = {bf.x, bf.y, bf.z, bf.w};
#pragma unroll
            for (int i = 0; i < 4; i++)
#pragma unroll
                for (int j = 0; j < 4; j++)
                    s[i][j] += af[i] * bfr[j];
        }

        // ---- online softmax over this 64-col slab ----
        bool cmask[4];
#pragma unroll
        for (int j = 0; j < 4; j++) cmask[j] = (ms[tx * 4 + j] != 0);

        float corr[4];
#pragma unroll
        for (int i = 0; i < 4; i++) {
            float rmax = -1e30f;
#pragma unroll
            for (int j = 0; j < 4; j++) {
                float se = cmask[j] ? -1e30f : s[i][j] * scale;
                s[i][j] = se;
                rmax = fmaxf(rmax, se);
            }
#pragma unroll
            for (int off = 1; off < 16; off <<= 1)
                rmax = fmaxf(rmax, __shfl_xor_sync(0xffffffffu, rmax, off));

            float mnew = fmaxf(mrow[i], rmax);
            corr[i] = __expf(mrow[i] - mnew);   // 0 if first real data, 1 if no change
            float rsum = 0.f;
#pragma unroll
            for (int j = 0; j < 4; j++) {
                float p = cmask[j] ? 0.f : __expf(s[i][j] - mnew);
                s[i][j] = p;
                rsum += p;
            }
#pragma unroll
            for (int off = 1; off < 16; off <<= 1)
                rsum += __shfl_xor_sync(0xffffffffu, rsum, off);

            lrow[i] = lrow[i] * corr[i] + rsum;
            mrow[i] = mnew;
#pragma unroll
            for (int j = 0; j < 4; j++) acc[i][j] *= corr[i];
        }

        __syncthreads();  // all QK reads of KPt done before Pt overwrite

        // ---- write P transposed: Pt[c][r] (reuse KPt buffer) ----
#pragma unroll
        for (int j = 0; j < 4; j++) {
            float4 pv = make_float4(s[0][j], s[1][j], s[2][j], s[3][j]);
            *(float4*)&KPt[(tx * 4 + j) * PAD + ty * 4] = pv;
        }
        __syncthreads();

        // ---- PV: acc[i][j] += sum_c Pt[c][ty4+i] * Vs[c][tx4+j] ----
#pragma unroll
        for (int c = 0; c < QTILE; c++) {
            float4 a = *(const float4*)&KPt[c * PAD + ty * 4];
            float4 bf = *(const float4*)&Vs[c * PAD + tx * 4];
            float af[4] = {a.x, a.y, a.z, a.w};
            float bfr[4] = {bf.x, bf.y, bf.z, bf.w};
#pragma unroll
            for (int i = 0; i < 4; i++)
#pragma unroll
                for (int j = 0; j < 4; j++)
                    acc[i][j] += af[i] * bfr[j];
        }
    }

    // ---- epilogue: normalize, store ----
#pragma unroll
    for (int i = 0; i < 4; i++) {
        float inv = (lrow[i] > 0.f) ? (1.f / lrow[i]) : 0.f;
        int r = q0 + ty * 4 + i;
        float4 o;
        o.x = acc[i][0] * inv;
        o.y = acc[i][1] * inv;
        o.z = acc[i][2] * inv;
        o.w = acc[i][3] * inv;
        *(float4*)&Ctx[((size_t)b * S + r) * D + h * DK + tx * 4] = o;
    }
}

// ---------------- launch ----------------
extern "C" void kernel_launch(void* const* d_in, const int* in_sizes, int n_in,
                              void* d_out, int out_size)
{
    // metadata order: query, key, value, mask, Wq, bq, Wk, bk, Wv, bv, Wo, bo
    const float* query = (const float*)d_in[0];
    const float* key   = (const float*)d_in[1];
    const float* value = (const float*)d_in[2];
    const int*   mask  = (const int*)d_in[3];
    const float* Wq = (const float*)d_in[4];
    const float* bq = (const float*)d_in[5];
    const float* Wk = (const float*)d_in[6];
    const float* bk = (const float*)d_in[7];
    const float* Wv = (const float*)d_in[8];
    const float* bv = (const float*)d_in[9];
    const float* Wo = (const float*)d_in[10];
    const float* bo = (const float*)d_in[11];
    float* out = (float*)d_out;

    float *qbuf, *kbuf, *vbuf, *cbuf;
    cudaGetSymbolAddress((void**)&qbuf, g_Q);
    cudaGetSymbolAddress((void**)&kbuf, g_K);
    cudaGetSymbolAddress((void**)&vbuf, g_V);
    cudaGetSymbolAddress((void**)&cbuf, g_C);

    const int attn_smem = (3 * QTILE * PAD) * 4 + QTILE * 4;  // 52480 B
    static int smem_set = 0;
    if (!smem_set) {
        cudaFuncSetAttribute(attention_kernel,
                             cudaFuncAttributeMaxDynamicSharedMemorySize, attn_smem);
        smem_set = 1;
    }

    dim3 gemm_grid(D / BN, M_ROWS / BM);   // (8, 32)
    gemm_bias_kernel<<<gemm_grid, 256>>>(query, Wq, bq, qbuf, M_ROWS, D, D);
    gemm_bias_kernel<<<gemm_grid, 256>>>(key,   Wk, bk, kbuf, M_ROWS, D, D);
    gemm_bias_kernel<<<gemm_grid, 256>>>(value, Wv, bv, vbuf, M_ROWS, D, D);

    dim3 attn_grid(S / QTILE, H, B);       // (32, 16, 2)
    attention_kernel<<<attn_grid, 256, attn_smem>>>(qbuf, kbuf, vbuf, mask, cbuf);

    gemm_bias_kernel<<<gemm_grid, 256>>>(cbuf, Wo, bo, out, M_ROWS, D, D);
}